// round 8
// baseline (speedup 1.0000x reference)
#include <cuda_runtime.h>
#include <cuda_bf16.h>
#include <mma.h>
#include <math.h>
#include <stdint.h>

using namespace nvcuda;

#define NN 100000
#define EE 3200000
#define IN_DIM 512
#define H1 64
#define H2 32
#define H3 16
#define OUTD 40
#define BN_EPS 1e-5f

// ---------------- scratch (device globals: allocation-free) ----------------
__device__ float g_sup1[NN * H1];
__device__ float g_h1  [NN * H1];
__device__ float g_sup2[NN * H2];
__device__ float g_h2  [NN * H2];
__device__ float g_sup3[NN * H3];
__device__ float g_h3  [NN * H3];
__device__ float g_sup4[NN * OUTD];
__device__ int   g_rowptr[NN + 1];
__device__ float g_stats[384];   // A(+0), B(+128), C(+256): sum[f], sumsq[64+f]

// ---------------- setup: zero stats + CSR rowptr (edge_row sorted) ----------------
__global__ void setup_kernel(const int* __restrict__ row, int n, int e) {
    int z = blockIdx.x * blockDim.x + threadIdx.x;
    if (z < 384) g_stats[z] = 0.f;
    int i = z;
    if (i >= e) return;
    int r = row[i];
    int prev = (i == 0) ? -1 : row[i - 1];
    for (int q = prev + 1; q <= r; q++) g_rowptr[q] = i;
    if (i == e - 1) {
        for (int q = r + 1; q <= n; q++) g_rowptr[q] = e;
    }
}

// ---------------- WMMA bf16-split GEMM: C[n x 64] = A[n x 512] @ W[512 x 64] ----------------
// Block tile 128x64, BK=32, 256 threads (8 warps), warp tile 16x64.
// Split: C = Ahi@Whi + Ahi@Wlo + Alo@Whi, fp32 accumulators.
#define GBM 128
#define GBN 64
#define GBK 32

__global__ __launch_bounds__(256) void gemm_wmma_kernel(
    const float* __restrict__ A, const float* __restrict__ W,
    float* __restrict__ C, int n)
{
    // compute phase uses 24KB; epilogue staging reuses it as 32KB float buffer
    __shared__ __align__(16) char smemraw[32768];
    __nv_bfloat16* sAhi = reinterpret_cast<__nv_bfloat16*>(smemraw);             // 128*32*2 = 8KB
    __nv_bfloat16* sAlo = reinterpret_cast<__nv_bfloat16*>(smemraw + 8192);      // 8KB
    __nv_bfloat16* sBhi = reinterpret_cast<__nv_bfloat16*>(smemraw + 16384);     // 32*64*2 = 4KB
    __nv_bfloat16* sBlo = reinterpret_cast<__nv_bfloat16*>(smemraw + 20480);     // 4KB

    int tid = threadIdx.x;
    int wid = tid >> 5;
    int rowBase = blockIdx.x * GBM;

    wmma::fragment<wmma::accumulator, 16, 16, 16, float> acc[4];
    #pragma unroll
    for (int j = 0; j < 4; j++) wmma::fill_fragment(acc[j], 0.0f);

    for (int k0 = 0; k0 < IN_DIM; k0 += GBK) {
        // ---- A tile: 128x32 fp32 -> hi/lo bf16 (row-major, ld=32) ----
        #pragma unroll
        for (int u = 0; u < 4; u++) {
            int idx = tid * 4 + u;          // 0..1023 float4 slots
            int r   = idx >> 3;             // 0..127
            int c4  = idx & 7;              // 0..7
            float4 v = make_float4(0.f, 0.f, 0.f, 0.f);
            if (rowBase + r < n)
                v = *reinterpret_cast<const float4*>(A + (size_t)(rowBase + r) * IN_DIM + k0 + c4 * 4);
            __nv_bfloat162 h01 = __floats2bfloat162_rn(v.x, v.y);
            __nv_bfloat162 h23 = __floats2bfloat162_rn(v.z, v.w);
            float l0 = v.x - __bfloat162float(__low2bfloat16(h01));
            float l1 = v.y - __bfloat162float(__high2bfloat16(h01));
            float l2 = v.z - __bfloat162float(__low2bfloat16(h23));
            float l3 = v.w - __bfloat162float(__high2bfloat16(h23));
            __nv_bfloat162 o01 = __floats2bfloat162_rn(l0, l1);
            __nv_bfloat162 o23 = __floats2bfloat162_rn(l2, l3);
            uint2 hb, lb;
            hb.x = *reinterpret_cast<uint32_t*>(&h01); hb.y = *reinterpret_cast<uint32_t*>(&h23);
            lb.x = *reinterpret_cast<uint32_t*>(&o01); lb.y = *reinterpret_cast<uint32_t*>(&o23);
            *reinterpret_cast<uint2*>(sAhi + r * GBK + c4 * 4) = hb;
            *reinterpret_cast<uint2*>(sAlo + r * GBK + c4 * 4) = lb;
        }
        // ---- W chunk: 32x64 fp32 -> hi/lo bf16 (row-major, ld=64) ----
        #pragma unroll
        for (int u = 0; u < 2; u++) {
            int idx = tid * 2 + u;          // 0..511 float4 slots
            int kr  = idx >> 4;             // 0..31
            int c4  = idx & 15;             // 0..15
            float4 v = *reinterpret_cast<const float4*>(W + (size_t)(k0 + kr) * GBN + c4 * 4);
            __nv_bfloat162 h01 = __floats2bfloat162_rn(v.x, v.y);
            __nv_bfloat162 h23 = __floats2bfloat162_rn(v.z, v.w);
            float l0 = v.x - __bfloat162float(__low2bfloat16(h01));
            float l1 = v.y - __bfloat162float(__high2bfloat16(h01));
            float l2 = v.z - __bfloat162float(__low2bfloat16(h23));
            float l3 = v.w - __bfloat162float(__high2bfloat16(h23));
            __nv_bfloat162 o01 = __floats2bfloat162_rn(l0, l1);
            __nv_bfloat162 o23 = __floats2bfloat162_rn(l2, l3);
            uint2 hb, lb;
            hb.x = *reinterpret_cast<uint32_t*>(&h01); hb.y = *reinterpret_cast<uint32_t*>(&h23);
            lb.x = *reinterpret_cast<uint32_t*>(&o01); lb.y = *reinterpret_cast<uint32_t*>(&o23);
            *reinterpret_cast<uint2*>(sBhi + kr * GBN + c4 * 4) = hb;
            *reinterpret_cast<uint2*>(sBlo + kr * GBN + c4 * 4) = lb;
        }
        __syncthreads();

        #pragma unroll
        for (int kk = 0; kk < 2; kk++) {
            wmma::fragment<wmma::matrix_a, 16, 16, 16, __nv_bfloat16, wmma::row_major> a_hi, a_lo;
            wmma::load_matrix_sync(a_hi, sAhi + (wid * 16) * GBK + kk * 16, GBK);
            wmma::load_matrix_sync(a_lo, sAlo + (wid * 16) * GBK + kk * 16, GBK);
            #pragma unroll
            for (int j = 0; j < 4; j++) {
                wmma::fragment<wmma::matrix_b, 16, 16, 16, __nv_bfloat16, wmma::row_major> b_hi, b_lo;
                wmma::load_matrix_sync(b_hi, sBhi + (kk * 16) * GBN + j * 16, GBN);
                wmma::load_matrix_sync(b_lo, sBlo + (kk * 16) * GBN + j * 16, GBN);
                wmma::mma_sync(acc[j], a_hi, b_hi, acc[j]);
                wmma::mma_sync(acc[j], a_hi, b_lo, acc[j]);
                wmma::mma_sync(acc[j], a_lo, b_hi, acc[j]);
            }
        }
        __syncthreads();
    }

    // ---- epilogue ----
    if (rowBase + GBM <= n) {
        // full tile: direct stores
        float* cw = C + (size_t)(rowBase + wid * 16) * GBN;
        #pragma unroll
        for (int j = 0; j < 4; j++)
            wmma::store_matrix_sync(cw + j * 16, acc[j], GBN, wmma::mem_row_major);
    } else {
        // boundary tile: stage via smem, guarded copy
        float* sC = reinterpret_cast<float*>(smemraw);   // 128*64*4 = 32KB
        float* cw = sC + (size_t)(wid * 16) * GBN;
        #pragma unroll
        for (int j = 0; j < 4; j++)
            wmma::store_matrix_sync(cw + j * 16, acc[j], GBN, wmma::mem_row_major);
        __syncthreads();
        for (int idx = tid; idx < GBM * GBN; idx += 256) {
            int r = idx >> 6;
            int c = idx & 63;
            if (rowBase + r < n)
                C[(size_t)(rowBase + r) * GBN + c] = sC[idx];
        }
    }
}

// ---------------- persistent SpMM fused with BN-stats accumulation ----------------
template <int F>
__global__ __launch_bounds__(256) void spmm_stats_kernel(
    const float* __restrict__ sup, const int* __restrict__ col,
    const float* __restrict__ val, float* __restrict__ out,
    float* __restrict__ stats, int n)
{
    int wid  = threadIdx.x >> 5;
    int lane = threadIdx.x & 31;

    if constexpr (F == 64) {
        __shared__ float sm[8][64];
        const float2* s2 = reinterpret_cast<const float2*>(sup);
        float2* o2 = reinterpret_cast<float2*>(out);
        float sx = 0.f, sy = 0.f, qx = 0.f, qy = 0.f;
        for (int r = blockIdx.x * 8 + wid; r < n; r += gridDim.x * 8) {
            int e = g_rowptr[r], eend = g_rowptr[r + 1];
            float2 acc = make_float2(0.f, 0.f);
            #pragma unroll 4
            for (; e < eend; e++) {
                int   c = __ldg(col + e);
                float v = __ldg(val + e);
                float2 sv = __ldg(s2 + (size_t)c * 32 + lane);
                acc.x += v * sv.x;
                acc.y += v * sv.y;
            }
            o2[(size_t)r * 32 + lane] = acc;
            sx += acc.x; sy += acc.y;
            qx += acc.x * acc.x; qy += acc.y * acc.y;
        }
        sm[wid][2 * lane] = sx; sm[wid][2 * lane + 1] = sy;
        __syncthreads();
        if (threadIdx.x < 64) {
            float s = 0.f;
            #pragma unroll
            for (int w = 0; w < 8; w++) s += sm[w][threadIdx.x];
            atomicAdd(&stats[threadIdx.x], s);
        }
        __syncthreads();
        sm[wid][2 * lane] = qx; sm[wid][2 * lane + 1] = qy;
        __syncthreads();
        if (threadIdx.x < 64) {
            float s = 0.f;
            #pragma unroll
            for (int w = 0; w < 8; w++) s += sm[w][threadIdx.x];
            atomicAdd(&stats[64 + threadIdx.x], s);
        }
    } else if constexpr (F == 32) {
        __shared__ float sm[8][32];
        float sx = 0.f, qx = 0.f;
        for (int r = blockIdx.x * 8 + wid; r < n; r += gridDim.x * 8) {
            int e = g_rowptr[r], eend = g_rowptr[r + 1];
            float acc = 0.f;
            #pragma unroll 4
            for (; e < eend; e++) {
                int   c = __ldg(col + e);
                float v = __ldg(val + e);
                acc += v * __ldg(sup + (size_t)c * 32 + lane);
            }
            out[(size_t)r * 32 + lane] = acc;
            sx += acc; qx += acc * acc;
        }
        sm[wid][lane] = sx;
        __syncthreads();
        if (threadIdx.x < 32) {
            float s = 0.f;
            #pragma unroll
            for (int w = 0; w < 8; w++) s += sm[w][threadIdx.x];
            atomicAdd(&stats[threadIdx.x], s);
        }
        __syncthreads();
        sm[wid][lane] = qx;
        __syncthreads();
        if (threadIdx.x < 32) {
            float s = 0.f;
            #pragma unroll
            for (int w = 0; w < 8; w++) s += sm[w][threadIdx.x];
            atomicAdd(&stats[64 + threadIdx.x], s);
        }
    } else {  // F == 16: two rows per warp (half-warps)
        __shared__ float sm[8][32];
        int half = lane >> 4;
        int f    = lane & 15;
        float sx = 0.f, qx = 0.f;
        for (int r = blockIdx.x * 16 + wid * 2 + half; r < n; r += gridDim.x * 16) {
            int e = g_rowptr[r], eend = g_rowptr[r + 1];
            float acc = 0.f;
            #pragma unroll 4
            for (; e < eend; e++) {
                int   c = __ldg(col + e);
                float v = __ldg(val + e);
                acc += v * __ldg(sup + (size_t)c * 16 + f);
            }
            out[(size_t)r * 16 + f] = acc;
            sx += acc; qx += acc * acc;
        }
        sm[wid][lane] = sx;
        __syncthreads();
        if (threadIdx.x < 16) {
            float s = 0.f;
            #pragma unroll
            for (int w = 0; w < 8; w++) s += sm[w][threadIdx.x] + sm[w][threadIdx.x + 16];
            atomicAdd(&stats[threadIdx.x], s);
        }
        __syncthreads();
        sm[wid][lane] = qx;
        __syncthreads();
        if (threadIdx.x < 16) {
            float s = 0.f;
            #pragma unroll
            for (int w = 0; w < 8; w++) s += sm[w][threadIdx.x] + sm[w][threadIdx.x + 16];
            atomicAdd(&stats[64 + threadIdx.x], s);
        }
    }
}

// ---------------- fused BN+ELU+GEMM: C[n x M] = elu(bn(A)) @ W  (row per thread) ----------------
template <int K, int M>
__global__ __launch_bounds__(256) void bn_gemm_kernel(
    const float* __restrict__ A, const float* __restrict__ stats,
    const float* __restrict__ gamma, const float* __restrict__ beta,
    const float* __restrict__ W, float* __restrict__ C, int n)
{
    __shared__ float sW[K * M];
    __shared__ float sScale[K], sShift[K];

    for (int i = threadIdx.x; i < K * M; i += blockDim.x) sW[i] = W[i];
    if (threadIdx.x < K) {
        int f = threadIdx.x;
        float invN = 1.f / (float)n;
        float mean = stats[f] * invN;
        float var  = stats[64 + f] * invN - mean * mean;
        float inv  = rsqrtf(var + BN_EPS);
        float sc = inv * gamma[f];
        sScale[f] = sc;
        sShift[f] = beta[f] - mean * sc;
    }
    __syncthreads();

    int r = blockIdx.x * blockDim.x + threadIdx.x;
    if (r >= n) return;

    const float4* a4 = reinterpret_cast<const float4*>(A + (size_t)r * K);
    float acc[M];
    #pragma unroll
    for (int m = 0; m < M; m++) acc[m] = 0.f;

    #pragma unroll
    for (int kc = 0; kc < K / 4; kc++) {
        float4 v = __ldg(a4 + kc);
        float a[4] = {v.x, v.y, v.z, v.w};
        #pragma unroll
        for (int j = 0; j < 4; j++) {
            int k = kc * 4 + j;
            float t = a[j] * sScale[k] + sShift[k];
            t = (t > 0.f) ? t : expm1f(t);
            #pragma unroll
            for (int m = 0; m < M; m++)
                acc[m] += t * sW[k * M + m];
        }
    }

    float4* c4 = reinterpret_cast<float4*>(C + (size_t)r * M);
    #pragma unroll
    for (int m = 0; m < M / 4; m++)
        c4[m] = make_float4(acc[4 * m], acc[4 * m + 1], acc[4 * m + 2], acc[4 * m + 3]);
}

// ---------------- final SpMM (F=40) fused with log_softmax -> d_out ----------------
__global__ __launch_bounds__(256) void spmm40_logsoftmax_kernel(
    const float* __restrict__ sup, const int* __restrict__ col,
    const float* __restrict__ val, float* __restrict__ out, int n)
{
    int gw = (blockIdx.x * blockDim.x + threadIdx.x) >> 5;
    int lane = threadIdx.x & 31;
    if (gw >= n) return;
    int e = g_rowptr[gw], eend = g_rowptr[gw + 1];
    bool second = (lane < 8);
    float a0 = 0.f, a1 = 0.f;
    #pragma unroll 2
    for (; e < eend; e++) {
        int   c = __ldg(col + e);
        float v = __ldg(val + e);
        a0 += v * __ldg(sup + (size_t)c * 40 + lane);
        if (second) a1 += v * __ldg(sup + (size_t)c * 40 + 32 + lane);
    }
    float m = a0;
    if (second) m = fmaxf(m, a1);
    #pragma unroll
    for (int off = 16; off > 0; off >>= 1)
        m = fmaxf(m, __shfl_xor_sync(0xffffffffu, m, off));
    float s = __expf(a0 - m);
    if (second) s += __expf(a1 - m);
    #pragma unroll
    for (int off = 16; off > 0; off >>= 1)
        s += __shfl_xor_sync(0xffffffffu, s, off);
    float lse = m + logf(s);
    out[(size_t)gw * 40 + lane] = a0 - lse;
    if (second) out[(size_t)gw * 40 + 32 + lane] = a1 - lse;
}

// ---------------- launch ----------------
extern "C" void kernel_launch(void* const* d_in, const int* in_sizes, int n_in,
                              void* d_out, int out_size) {
    const float* x        = (const float*)d_in[0];
    const int*   edge_row = (const int*)  d_in[1];
    const int*   edge_col = (const int*)  d_in[2];
    const float* edge_val = (const float*)d_in[3];
    const float* W1 = (const float*)d_in[4];
    const float* W2 = (const float*)d_in[5];
    const float* W3 = (const float*)d_in[6];
    const float* W4 = (const float*)d_in[7];
    const float* g1 = (const float*)d_in[8];
    const float* b1 = (const float*)d_in[9];
    const float* g2 = (const float*)d_in[10];
    const float* b2 = (const float*)d_in[11];
    const float* g3 = (const float*)d_in[12];
    const float* b3 = (const float*)d_in[13];
    float* out = (float*)d_out;

    int n = in_sizes[0] / IN_DIM;   // 100000
    int e = in_sizes[1];            // 3200000

    float* sup1; cudaGetSymbolAddress((void**)&sup1, g_sup1);
    float* h1;   cudaGetSymbolAddress((void**)&h1,   g_h1);
    float* sup2; cudaGetSymbolAddress((void**)&sup2, g_sup2);
    float* h2;   cudaGetSymbolAddress((void**)&h2,   g_h2);
    float* sup3; cudaGetSymbolAddress((void**)&sup3, g_sup3);
    float* h3;   cudaGetSymbolAddress((void**)&h3,   g_h3);
    float* sup4; cudaGetSymbolAddress((void**)&sup4, g_sup4);
    float* stats; cudaGetSymbolAddress((void**)&stats, g_stats);
    float* stA = stats, *stB = stats + 128, *stC = stats + 256;

    const int SPMM_GRID = 592;  // 4 blocks/SM

    // 1: rowptr + zero stats
    setup_kernel<<<(e + 255) / 256, 256>>>(edge_row, n, e);
    // 2: layer-1 dense GEMM (WMMA bf16-split HMMA)
    gemm_wmma_kernel<<<(n + GBM - 1) / GBM, 256>>>(x, W1, sup1, n);
    // 3: SpMM(64) + stats A
    spmm_stats_kernel<64><<<SPMM_GRID, 256>>>(sup1, edge_col, edge_val, h1, stA, n);
    // 4: bn_elu(A) + GEMM 64->32
    bn_gemm_kernel<64, 32><<<(n + 255) / 256, 256>>>(h1, stA, g1, b1, W2, sup2, n);
    // 5: SpMM(32) + stats B
    spmm_stats_kernel<32><<<SPMM_GRID, 256>>>(sup2, edge_col, edge_val, h2, stB, n);
    // 6: bn_elu(B) + GEMM 32->16
    bn_gemm_kernel<32, 16><<<(n + 255) / 256, 256>>>(h2, stB, g2, b2, W3, sup3, n);
    // 7: SpMM(16) + stats C
    spmm_stats_kernel<16><<<SPMM_GRID, 256>>>(sup3, edge_col, edge_val, h3, stC, n);
    // 8: bn_elu(C) + GEMM 16->40
    bn_gemm_kernel<16, 40><<<(n + 255) / 256, 256>>>(h3, stC, g3, b3, W4, sup4, n);
    // 9: SpMM(40) + log_softmax
    spmm40_logsoftmax_kernel<<<((size_t)n * 32 + 255) / 256, 256>>>(sup4, edge_col, edge_val, out, n);
}

// round 9
// speedup vs baseline: 1.7822x; 1.7822x over previous
#include <cuda_runtime.h>
#include <cuda_bf16.h>
#include <math.h>
#include <stdint.h>

#define NN 100000
#define EE 3200000
#define IN_DIM 512
#define H1 64
#define H2 32
#define H3 16
#define OUTD 40
#define BN_EPS 1e-5f

// ---------------- scratch (device globals: allocation-free) ----------------
__device__ float g_sup1[NN * H1];
__device__ float g_h1  [NN * H1];
__device__ float g_sup2[NN * H2];
__device__ float g_h2  [NN * H2];
__device__ float g_sup3[NN * H3];
__device__ float g_h3  [NN * H3];
__device__ float g_sup4[NN * OUTD];
__device__ int   g_rowptr[NN + 1];
__device__ float g_stats[384];   // A(+0), B(+128), C(+256): sum[f], sumsq[64+f]

// ---------------- f32x2 packed helpers ----------------
__device__ __forceinline__ unsigned long long pack2_dup(float v) {
    unsigned long long r;
    asm("mov.b64 %0, {%1, %1};" : "=l"(r) : "f"(v));
    return r;
}
__device__ __forceinline__ unsigned long long fma2(unsigned long long a,
                                                   unsigned long long b,
                                                   unsigned long long c) {
    unsigned long long d;
    asm("fma.rn.f32x2 %0, %1, %2, %3;" : "=l"(d) : "l"(a), "l"(b), "l"(c));
    return d;
}
__device__ __forceinline__ void unpack2(unsigned long long v, float& lo, float& hi) {
    asm("mov.b64 {%0, %1}, %2;" : "=f"(lo), "=f"(hi) : "l"(v));
}

// ---------------- setup: zero stats + CSR rowptr (edge_row sorted) ----------------
__global__ void setup_kernel(const int* __restrict__ row, int n, int e) {
    int z = blockIdx.x * blockDim.x + threadIdx.x;
    if (z < 384) g_stats[z] = 0.f;
    int i = z;
    if (i >= e) return;
    int r = row[i];
    int prev = (i == 0) ? -1 : row[i - 1];
    for (int q = prev + 1; q <= r; q++) g_rowptr[q] = i;
    if (i == e - 1) {
        for (int q = r + 1; q <= n; q++) g_rowptr[q] = e;
    }
}

// ---------------- big GEMM (f32x2): C[n x 64] = A[n x 512] @ W[512 x 64] ----------------
// Block 256x64, 128 threads, BK=16. Thread tile 16 rows x 8 cols.
// A transposed in smem [k][row] (pairs = consecutive rows); B duplicated u64.
// ty = tid>>3 (0..15): rows g*64 + ty*4 + {0..3}, g=0..3  (A reads conflict-free: warp spans 4 ty)
// tx = tid&7  (0..7):  cols h*16 + tx*2 + {0,1},  h=0..3  (B reads exactly 128B/warp)
#define TBM 256
#define TBN 64
#define TBK 16
#define APAD 260   // 256 + 4 floats pad  -> 1040B row (16B aligned, bank-shifts k-planes)
#define BPAD 66    // 64 + 2 u64 pad      -> 528B row (16B aligned)

__global__ __launch_bounds__(128) void gemm_f32x2_kernel(
    const float* __restrict__ A, const float* __restrict__ W,
    float* __restrict__ C, int n)
{
    __shared__ __align__(16) float As[TBK][APAD];                 // 16.6 KB
    __shared__ __align__(16) unsigned long long Bd[TBK][BPAD];    //  8.4 KB

    int tid = threadIdx.x;
    int ty = tid >> 3;
    int tx = tid & 7;
    int rowBase = blockIdx.x * TBM;

    unsigned long long acc[4][2][8];   // [g][pair][h*2+j]
    #pragma unroll
    for (int g = 0; g < 4; g++)
        #pragma unroll
        for (int p = 0; p < 2; p++)
            #pragma unroll
            for (int c = 0; c < 8; c++) acc[g][p][c] = 0ULL;

    for (int k0 = 0; k0 < IN_DIM; k0 += TBK) {
        // ---- load A tile 256x16 (transpose to [k][row]) ----
        #pragma unroll
        for (int u = 0; u < 8; u++) {
            int slot = u * 128 + tid;          // 0..1023
            int r  = slot >> 2;                // 0..255
            int c4 = slot & 3;                 // float4 index along k
            float4 v = make_float4(0.f, 0.f, 0.f, 0.f);
            if (rowBase + r < n)
                v = *reinterpret_cast<const float4*>(A + (size_t)(rowBase + r) * IN_DIM + k0 + c4 * 4);
            As[c4 * 4 + 0][r] = v.x;
            As[c4 * 4 + 1][r] = v.y;
            As[c4 * 4 + 2][r] = v.z;
            As[c4 * 4 + 3][r] = v.w;
        }
        // ---- load B chunk 16x64, duplicated u64 ----
        #pragma unroll
        for (int u = 0; u < 8; u++) {
            int slot = u * 128 + tid;          // 0..1023
            int kr = slot >> 6;                // 0..15
            int c  = slot & 63;                // 0..63
            Bd[kr][c] = pack2_dup(__ldg(W + (size_t)(k0 + kr) * TBN + c));
        }
        __syncthreads();

        #pragma unroll
        for (int kk = 0; kk < TBK; kk++) {
            // A pairs: 4 groups x LDS.128 (4 rows -> 2 pairs)
            unsigned long long ap[4][2];
            #pragma unroll
            for (int g = 0; g < 4; g++) {
                ulonglong2 v = *reinterpret_cast<const ulonglong2*>(&As[kk][g * 64 + ty * 4]);
                ap[g][0] = v.x;   // rows +0,+1
                ap[g][1] = v.y;   // rows +2,+3
            }
            // B dups: 4 groups x LDS.128 (2 cols each)
            unsigned long long bd[4][2];
            #pragma unroll
            for (int h = 0; h < 4; h++) {
                ulonglong2 v = *reinterpret_cast<const ulonglong2*>(&Bd[kk][h * 16 + tx * 2]);
                bd[h][0] = v.x;
                bd[h][1] = v.y;
            }
            #pragma unroll
            for (int g = 0; g < 4; g++)
                #pragma unroll
                for (int p = 0; p < 2; p++)
                    #pragma unroll
                    for (int h = 0; h < 4; h++) {
                        acc[g][p][h * 2 + 0] = fma2(ap[g][p], bd[h][0], acc[g][p][h * 2 + 0]);
                        acc[g][p][h * 2 + 1] = fma2(ap[g][p], bd[h][1], acc[g][p][h * 2 + 1]);
                    }
        }
        __syncthreads();
    }

    // ---- epilogue: unpack pairs (rows) and store 2-float chunks ----
    #pragma unroll
    for (int g = 0; g < 4; g++) {
        #pragma unroll
        for (int p = 0; p < 2; p++) {
            int r0 = rowBase + g * 64 + ty * 4 + 2 * p;
            #pragma unroll
            for (int h = 0; h < 4; h++) {
                float l0, h0, l1, h1;
                unpack2(acc[g][p][h * 2 + 0], l0, h0);
                unpack2(acc[g][p][h * 2 + 1], l1, h1);
                int c = h * 16 + tx * 2;
                if (r0 < n)
                    *reinterpret_cast<float2*>(C + (size_t)r0 * TBN + c) = make_float2(l0, l1);
                if (r0 + 1 < n)
                    *reinterpret_cast<float2*>(C + (size_t)(r0 + 1) * TBN + c) = make_float2(h0, h1);
            }
        }
    }
}

// ---------------- persistent SpMM fused with BN-stats accumulation ----------------
template <int F>
__global__ __launch_bounds__(256) void spmm_stats_kernel(
    const float* __restrict__ sup, const int* __restrict__ col,
    const float* __restrict__ val, float* __restrict__ out,
    float* __restrict__ stats, int n)
{
    int wid  = threadIdx.x >> 5;
    int lane = threadIdx.x & 31;

    if constexpr (F == 64) {
        __shared__ float sm[8][64];
        const float2* s2 = reinterpret_cast<const float2*>(sup);
        float2* o2 = reinterpret_cast<float2*>(out);
        float sx = 0.f, sy = 0.f, qx = 0.f, qy = 0.f;
        for (int r = blockIdx.x * 8 + wid; r < n; r += gridDim.x * 8) {
            int e = g_rowptr[r], eend = g_rowptr[r + 1];
            float2 acc = make_float2(0.f, 0.f);
            #pragma unroll 4
            for (; e < eend; e++) {
                int   c = __ldg(col + e);
                float v = __ldg(val + e);
                float2 sv = __ldg(s2 + (size_t)c * 32 + lane);
                acc.x += v * sv.x;
                acc.y += v * sv.y;
            }
            o2[(size_t)r * 32 + lane] = acc;
            sx += acc.x; sy += acc.y;
            qx += acc.x * acc.x; qy += acc.y * acc.y;
        }
        sm[wid][2 * lane] = sx; sm[wid][2 * lane + 1] = sy;
        __syncthreads();
        if (threadIdx.x < 64) {
            float s = 0.f;
            #pragma unroll
            for (int w = 0; w < 8; w++) s += sm[w][threadIdx.x];
            atomicAdd(&stats[threadIdx.x], s);
        }
        __syncthreads();
        sm[wid][2 * lane] = qx; sm[wid][2 * lane + 1] = qy;
        __syncthreads();
        if (threadIdx.x < 64) {
            float s = 0.f;
            #pragma unroll
            for (int w = 0; w < 8; w++) s += sm[w][threadIdx.x];
            atomicAdd(&stats[64 + threadIdx.x], s);
        }
    } else if constexpr (F == 32) {
        __shared__ float sm[8][32];
        float sx = 0.f, qx = 0.f;
        for (int r = blockIdx.x * 8 + wid; r < n; r += gridDim.x * 8) {
            int e = g_rowptr[r], eend = g_rowptr[r + 1];
            float acc = 0.f;
            #pragma unroll 4
            for (; e < eend; e++) {
                int   c = __ldg(col + e);
                float v = __ldg(val + e);
                acc += v * __ldg(sup + (size_t)c * 32 + lane);
            }
            out[(size_t)r * 32 + lane] = acc;
            sx += acc; qx += acc * acc;
        }
        sm[wid][lane] = sx;
        __syncthreads();
        if (threadIdx.x < 32) {
            float s = 0.f;
            #pragma unroll
            for (int w = 0; w < 8; w++) s += sm[w][threadIdx.x];
            atomicAdd(&stats[threadIdx.x], s);
        }
        __syncthreads();
        sm[wid][lane] = qx;
        __syncthreads();
        if (threadIdx.x < 32) {
            float s = 0.f;
            #pragma unroll
            for (int w = 0; w < 8; w++) s += sm[w][threadIdx.x];
            atomicAdd(&stats[64 + threadIdx.x], s);
        }
    } else {  // F == 16: two rows per warp (half-warps)
        __shared__ float sm[8][32];
        int half = lane >> 4;
        int f    = lane & 15;
        float sx = 0.f, qx = 0.f;
        for (int r = blockIdx.x * 16 + wid * 2 + half; r < n; r += gridDim.x * 16) {
            int e = g_rowptr[r], eend = g_rowptr[r + 1];
            float acc = 0.f;
            #pragma unroll 4
            for (; e < eend; e++) {
                int   c = __ldg(col + e);
                float v = __ldg(val + e);
                acc += v * __ldg(sup + (size_t)c * 16 + f);
            }
            out[(size_t)r * 16 + f] = acc;
            sx += acc; qx += acc * acc;
        }
        sm[wid][lane] = sx;
        __syncthreads();
        if (threadIdx.x < 16) {
            float s = 0.f;
            #pragma unroll
            for (int w = 0; w < 8; w++) s += sm[w][threadIdx.x] + sm[w][threadIdx.x + 16];
            atomicAdd(&stats[threadIdx.x], s);
        }
        __syncthreads();
        sm[wid][lane] = qx;
        __syncthreads();
        if (threadIdx.x < 16) {
            float s = 0.f;
            #pragma unroll
            for (int w = 0; w < 8; w++) s += sm[w][threadIdx.x] + sm[w][threadIdx.x + 16];
            atomicAdd(&stats[64 + threadIdx.x], s);
        }
    }
}

// ---------------- fused BN+ELU+GEMM (f32x2): C[n x M] = elu(bn(A)) @ W ----------------
template <int K, int M>
__global__ __launch_bounds__(256) void bn_gemm_kernel(
    const float* __restrict__ A, const float* __restrict__ stats,
    const float* __restrict__ gamma, const float* __restrict__ beta,
    const float* __restrict__ W, float* __restrict__ C, int n)
{
    __shared__ __align__(16) float sW[K * M];
    __shared__ float sScale[K], sShift[K];

    for (int i = threadIdx.x; i < K * M; i += blockDim.x) sW[i] = W[i];
    if (threadIdx.x < K) {
        int f = threadIdx.x;
        float invN = 1.f / (float)n;
        float mean = stats[f] * invN;
        float var  = stats[64 + f] * invN - mean * mean;
        float inv  = rsqrtf(var + BN_EPS);
        float sc = inv * gamma[f];
        sScale[f] = sc;
        sShift[f] = beta[f] - mean * sc;
    }
    __syncthreads();

    int r = blockIdx.x * blockDim.x + threadIdx.x;
    if (r >= n) return;

    const float4* a4 = reinterpret_cast<const float4*>(A + (size_t)r * K);
    const unsigned long long* sW2 = reinterpret_cast<const unsigned long long*>(sW);

    unsigned long long acc2[M / 2];
    #pragma unroll
    for (int m = 0; m < M / 2; m++) acc2[m] = 0ULL;

    #pragma unroll
    for (int kc = 0; kc < K / 4; kc++) {
        float4 v = __ldg(a4 + kc);
        float a[4] = {v.x, v.y, v.z, v.w};
        #pragma unroll
        for (int j = 0; j < 4; j++) {
            int k = kc * 4 + j;
            float t = a[j] * sScale[k] + sShift[k];
            t = (t > 0.f) ? t : expm1f(t);
            unsigned long long td = pack2_dup(t);
            #pragma unroll
            for (int m = 0; m < M / 2; m++)
                acc2[m] = fma2(td, sW2[k * (M / 2) + m], acc2[m]);
        }
    }

    unsigned long long* c2 = reinterpret_cast<unsigned long long*>(C + (size_t)r * M);
    #pragma unroll
    for (int m = 0; m < M / 2; m++) c2[m] = acc2[m];
}

// ---------------- final SpMM (F=40) fused with log_softmax -> d_out ----------------
__global__ __launch_bounds__(256) void spmm40_logsoftmax_kernel(
    const float* __restrict__ sup, const int* __restrict__ col,
    const float* __restrict__ val, float* __restrict__ out, int n)
{
    int gw = (blockIdx.x * blockDim.x + threadIdx.x) >> 5;
    int lane = threadIdx.x & 31;
    if (gw >= n) return;
    int e = g_rowptr[gw], eend = g_rowptr[gw + 1];
    bool second = (lane < 8);
    float a0 = 0.f, a1 = 0.f;
    #pragma unroll 2
    for (; e < eend; e++) {
        int   c = __ldg(col + e);
        float v = __ldg(val + e);
        a0 += v * __ldg(sup + (size_t)c * 40 + lane);
        if (second) a1 += v * __ldg(sup + (size_t)c * 40 + 32 + lane);
    }
    float m = a0;
    if (second) m = fmaxf(m, a1);
    #pragma unroll
    for (int off = 16; off > 0; off >>= 1)
        m = fmaxf(m, __shfl_xor_sync(0xffffffffu, m, off));
    float s = __expf(a0 - m);
    if (second) s += __expf(a1 - m);
    #pragma unroll
    for (int off = 16; off > 0; off >>= 1)
        s += __shfl_xor_sync(0xffffffffu, s, off);
    float lse = m + logf(s);
    out[(size_t)gw * 40 + lane] = a0 - lse;
    if (second) out[(size_t)gw * 40 + 32 + lane] = a1 - lse;
}

// ---------------- launch ----------------
extern "C" void kernel_launch(void* const* d_in, const int* in_sizes, int n_in,
                              void* d_out, int out_size) {
    const float* x        = (const float*)d_in[0];
    const int*   edge_row = (const int*)  d_in[1];
    const int*   edge_col = (const int*)  d_in[2];
    const float* edge_val = (const float*)d_in[3];
    const float* W1 = (const float*)d_in[4];
    const float* W2 = (const float*)d_in[5];
    const float* W3 = (const float*)d_in[6];
    const float* W4 = (const float*)d_in[7];
    const float* g1 = (const float*)d_in[8];
    const float* b1 = (const float*)d_in[9];
    const float* g2 = (const float*)d_in[10];
    const float* b2 = (const float*)d_in[11];
    const float* g3 = (const float*)d_in[12];
    const float* b3 = (const float*)d_in[13];
    float* out = (float*)d_out;

    int n = in_sizes[0] / IN_DIM;   // 100000
    int e = in_sizes[1];            // 3200000

    float* sup1; cudaGetSymbolAddress((void**)&sup1, g_sup1);
    float* h1;   cudaGetSymbolAddress((void**)&h1,   g_h1);
    float* sup2; cudaGetSymbolAddress((void**)&sup2, g_sup2);
    float* h2;   cudaGetSymbolAddress((void**)&h2,   g_h2);
    float* sup3; cudaGetSymbolAddress((void**)&sup3, g_sup3);
    float* h3;   cudaGetSymbolAddress((void**)&h3,   g_h3);
    float* sup4; cudaGetSymbolAddress((void**)&sup4, g_sup4);
    float* stats; cudaGetSymbolAddress((void**)&stats, g_stats);
    float* stA = stats, *stB = stats + 128, *stC = stats + 256;

    const int SPMM_GRID = 592;  // 4 blocks/SM

    // 1: rowptr + zero stats
    setup_kernel<<<(e + 255) / 256, 256>>>(edge_row, n, e);
    // 2: layer-1 dense GEMM (f32x2 packed, conflict-free smem)
    gemm_f32x2_kernel<<<(n + TBM - 1) / TBM, 128>>>(x, W1, sup1, n);
    // 3: SpMM(64) + stats A
    spmm_stats_kernel<64><<<SPMM_GRID, 256>>>(sup1, edge_col, edge_val, h1, stA, n);
    // 4: bn_elu(A) + GEMM 64->32
    bn_gemm_kernel<64, 32><<<(n + 255) / 256, 256>>>(h1, stA, g1, b1, W2, sup2, n);
    // 5: SpMM(32) + stats B
    spmm_stats_kernel<32><<<SPMM_GRID, 256>>>(sup2, edge_col, edge_val, h2, stB, n);
    // 6: bn_elu(B) + GEMM 32->16
    bn_gemm_kernel<32, 16><<<(n + 255) / 256, 256>>>(h2, stB, g2, b2, W3, sup3, n);
    // 7: SpMM(16) + stats C
    spmm_stats_kernel<16><<<SPMM_GRID, 256>>>(sup3, edge_col, edge_val, h3, stC, n);
    // 8: bn_elu(C) + GEMM 16->40
    bn_gemm_kernel<16, 40><<<(n + 255) / 256, 256>>>(h3, stC, g3, b3, W4, sup4, n);
    // 9: SpMM(40) + log_softmax
    spmm40_logsoftmax_kernel<<<((size_t)n * 32 + 255) / 256, 256>>>(sup4, edge_col, edge_val, out, n);
}

// round 10
// speedup vs baseline: 2.0239x; 1.1356x over previous
#include <cuda_runtime.h>
#include <cuda_bf16.h>
#include <math.h>
#include <stdint.h>

#define NN 100000
#define EE 3200000
#define IN_DIM 512
#define H1 64
#define H2 32
#define H3 16
#define OUTD 40
#define BN_EPS 1e-5f

// ---------------- scratch (device globals: allocation-free) ----------------
__device__ float g_sup1[NN * H1];
__device__ float g_h1  [NN * H1];
__device__ float g_sup2[NN * H2];
__device__ float g_h2  [NN * H2];
__device__ float g_sup3[NN * H3];
__device__ float g_h3  [NN * H3];
__device__ float g_h3n [NN * H3];
__device__ int   g_rowptr[NN + 1];
__device__ float g_stats[384];   // A(+0), B(+128), C(+256): sum[f], sumsq[64+f]

// ---------------- f32x2 packed helpers ----------------
__device__ __forceinline__ unsigned long long pack2_dup(float v) {
    unsigned long long r;
    asm("mov.b64 %0, {%1, %1};" : "=l"(r) : "f"(v));
    return r;
}
__device__ __forceinline__ unsigned long long fma2(unsigned long long a,
                                                   unsigned long long b,
                                                   unsigned long long c) {
    unsigned long long d;
    asm("fma.rn.f32x2 %0, %1, %2, %3;" : "=l"(d) : "l"(a), "l"(b), "l"(c));
    return d;
}

// ---------------- setup: zero stats + CSR rowptr (edge_row sorted) ----------------
__global__ void setup_kernel(const int* __restrict__ row, int n, int e) {
    int z = blockIdx.x * blockDim.x + threadIdx.x;
    if (z < 384) g_stats[z] = 0.f;
    int i = z;
    if (i >= e) return;
    int r = row[i];
    int prev = (i == 0) ? -1 : row[i - 1];
    for (int q = prev + 1; q <= r; q++) g_rowptr[q] = i;
    if (i == e - 1) {
        for (int q = r + 1; q <= n; q++) g_rowptr[q] = e;
    }
}

// ---------------- big GEMM: C[n x 64] = A[n x 512] @ B[512 x 64] ----------------
// BM=64, BN=64, BK=32, 256 threads, 4x4 micro-tile (fp32 FFMA roofline; R6-proven).
__global__ __launch_bounds__(256) void gemm512x64_kernel(
    const float* __restrict__ A, const float* __restrict__ B,
    float* __restrict__ C, int n)
{
    __shared__ __align__(16) float As[32][68];
    __shared__ __align__(16) float Bs[32][64];

    int tid = threadIdx.x;
    int tx = tid & 15;
    int ty = tid >> 4;
    int rowBase = blockIdx.x * 64;

    int ar  = tid >> 3;
    int ac4 = tid & 7;
    int bk  = tid >> 4;
    int bn4 = tid & 15;

    float acc[4][4] = {};

    for (int k0 = 0; k0 < IN_DIM; k0 += 32) {
        #pragma unroll
        for (int rr = 0; rr < 2; rr++) {
            int r = ar + rr * 32;
            int grow = rowBase + r;
            float4 v = make_float4(0.f, 0.f, 0.f, 0.f);
            if (grow < n)
                v = *reinterpret_cast<const float4*>(A + (size_t)grow * IN_DIM + k0 + ac4 * 4);
            As[ac4 * 4 + 0][r] = v.x;
            As[ac4 * 4 + 1][r] = v.y;
            As[ac4 * 4 + 2][r] = v.z;
            As[ac4 * 4 + 3][r] = v.w;
        }
        #pragma unroll
        for (int kk2 = 0; kk2 < 2; kk2++) {
            int k = bk + kk2 * 16;
            float4 v = *reinterpret_cast<const float4*>(B + (size_t)(k0 + k) * 64 + bn4 * 4);
            *reinterpret_cast<float4*>(&Bs[k][bn4 * 4]) = v;
        }
        __syncthreads();

        #pragma unroll
        for (int kk = 0; kk < 32; kk++) {
            float a[4], b[4];
            *reinterpret_cast<float4*>(a) = *reinterpret_cast<const float4*>(&As[kk][ty * 4]);
            *reinterpret_cast<float4*>(b) = *reinterpret_cast<const float4*>(&Bs[kk][tx * 4]);
            #pragma unroll
            for (int i = 0; i < 4; i++)
                #pragma unroll
                for (int j = 0; j < 4; j++)
                    acc[i][j] += a[i] * b[j];
        }
        __syncthreads();
    }

    #pragma unroll
    for (int i = 0; i < 4; i++) {
        int grow = rowBase + ty * 4 + i;
        if (grow < n) {
            *reinterpret_cast<float4*>(C + (size_t)grow * 64 + tx * 4) =
                make_float4(acc[i][0], acc[i][1], acc[i][2], acc[i][3]);
        }
    }
}

// ---------------- persistent SpMM fused with BN-stats accumulation ----------------
template <int F>
__global__ __launch_bounds__(256) void spmm_stats_kernel(
    const float* __restrict__ sup, const int* __restrict__ col,
    const float* __restrict__ val, float* __restrict__ out,
    float* __restrict__ stats, int n)
{
    int wid  = threadIdx.x >> 5;
    int lane = threadIdx.x & 31;

    if constexpr (F == 64) {
        __shared__ float sm[8][64];
        const float2* s2 = reinterpret_cast<const float2*>(sup);
        float2* o2 = reinterpret_cast<float2*>(out);
        float sx = 0.f, sy = 0.f, qx = 0.f, qy = 0.f;
        for (int r = blockIdx.x * 8 + wid; r < n; r += gridDim.x * 8) {
            int e = g_rowptr[r], eend = g_rowptr[r + 1];
            float2 acc = make_float2(0.f, 0.f);
            #pragma unroll 4
            for (; e < eend; e++) {
                int   c = __ldg(col + e);
                float v = __ldg(val + e);
                float2 sv = __ldg(s2 + (size_t)c * 32 + lane);
                acc.x += v * sv.x;
                acc.y += v * sv.y;
            }
            o2[(size_t)r * 32 + lane] = acc;
            sx += acc.x; sy += acc.y;
            qx += acc.x * acc.x; qy += acc.y * acc.y;
        }
        sm[wid][2 * lane] = sx; sm[wid][2 * lane + 1] = sy;
        __syncthreads();
        if (threadIdx.x < 64) {
            float s = 0.f;
            #pragma unroll
            for (int w = 0; w < 8; w++) s += sm[w][threadIdx.x];
            atomicAdd(&stats[threadIdx.x], s);
        }
        __syncthreads();
        sm[wid][2 * lane] = qx; sm[wid][2 * lane + 1] = qy;
        __syncthreads();
        if (threadIdx.x < 64) {
            float s = 0.f;
            #pragma unroll
            for (int w = 0; w < 8; w++) s += sm[w][threadIdx.x];
            atomicAdd(&stats[64 + threadIdx.x], s);
        }
    } else if constexpr (F == 32) {
        __shared__ float sm[8][32];
        float sx = 0.f, qx = 0.f;
        for (int r = blockIdx.x * 8 + wid; r < n; r += gridDim.x * 8) {
            int e = g_rowptr[r], eend = g_rowptr[r + 1];
            float acc = 0.f;
            #pragma unroll 4
            for (; e < eend; e++) {
                int   c = __ldg(col + e);
                float v = __ldg(val + e);
                acc += v * __ldg(sup + (size_t)c * 32 + lane);
            }
            out[(size_t)r * 32 + lane] = acc;
            sx += acc; qx += acc * acc;
        }
        sm[wid][lane] = sx;
        __syncthreads();
        if (threadIdx.x < 32) {
            float s = 0.f;
            #pragma unroll
            for (int w = 0; w < 8; w++) s += sm[w][threadIdx.x];
            atomicAdd(&stats[threadIdx.x], s);
        }
        __syncthreads();
        sm[wid][lane] = qx;
        __syncthreads();
        if (threadIdx.x < 32) {
            float s = 0.f;
            #pragma unroll
            for (int w = 0; w < 8; w++) s += sm[w][threadIdx.x];
            atomicAdd(&stats[64 + threadIdx.x], s);
        }
    } else {  // F == 16: two rows per warp (half-warps)
        __shared__ float sm[8][32];
        int half = lane >> 4;
        int f    = lane & 15;
        float sx = 0.f, qx = 0.f;
        for (int r = blockIdx.x * 16 + wid * 2 + half; r < n; r += gridDim.x * 16) {
            int e = g_rowptr[r], eend = g_rowptr[r + 1];
            float acc = 0.f;
            #pragma unroll 4
            for (; e < eend; e++) {
                int   c = __ldg(col + e);
                float v = __ldg(val + e);
                acc += v * __ldg(sup + (size_t)c * 16 + f);
            }
            out[(size_t)r * 16 + f] = acc;
            sx += acc; qx += acc * acc;
        }
        sm[wid][lane] = sx;
        __syncthreads();
        if (threadIdx.x < 16) {
            float s = 0.f;
            #pragma unroll
            for (int w = 0; w < 8; w++) s += sm[w][threadIdx.x] + sm[w][threadIdx.x + 16];
            atomicAdd(&stats[threadIdx.x], s);
        }
        __syncthreads();
        sm[wid][lane] = qx;
        __syncthreads();
        if (threadIdx.x < 16) {
            float s = 0.f;
            #pragma unroll
            for (int w = 0; w < 8; w++) s += sm[w][threadIdx.x] + sm[w][threadIdx.x + 16];
            atomicAdd(&stats[64 + threadIdx.x], s);
        }
    }
}

// ---------------- fused BN+ELU+GEMM, smem-staged: C[n x M] = elu(bn(A)) @ W ----------------
// 256 threads, 256 rows/block. A loaded coalesced into smem (KC=16 chunks),
// compute row-per-thread from smem, output staged through smem -> coalesced STG.
template <int K, int M>
__global__ __launch_bounds__(256) void bn_gemm_kernel(
    const float* __restrict__ A, const float* __restrict__ stats,
    const float* __restrict__ gamma, const float* __restrict__ beta,
    const float* __restrict__ W, float* __restrict__ C, int n)
{
    constexpr int KC = 16;
    constexpr int AROW = 260;                 // 256 + 4 pad floats
    constexpr int OROW = M + 2;               // output row stride (floats), even
    constexpr int ABYTES = KC * AROW * 4;
    constexpr int OBYTES = 256 * OROW * 4;
    constexpr int BUF = (ABYTES > OBYTES) ? ABYTES : OBYTES;
    __shared__ __align__(16) char buf[BUF];
    float (*As)[AROW] = reinterpret_cast<float(*)[AROW]>(buf);
    __shared__ __align__(16) float sW[K * M];
    __shared__ float sScale[K], sShift[K];

    int tid = threadIdx.x;
    int rowBase = blockIdx.x * 256;

    for (int i = tid; i < K * M; i += 256) sW[i] = W[i];
    if (tid < K) {
        float invN = 1.f / (float)n;
        float mean = stats[tid] * invN;
        float var  = stats[64 + tid] * invN - mean * mean;
        float inv  = rsqrtf(var + BN_EPS);
        float sc = inv * gamma[tid];
        sScale[tid] = sc;
        sShift[tid] = beta[tid] - mean * sc;
    }
    __syncthreads();

    const unsigned long long* sW2 = reinterpret_cast<const unsigned long long*>(sW);
    unsigned long long acc2[M / 2];
    #pragma unroll
    for (int m = 0; m < M / 2; m++) acc2[m] = 0ULL;

    #pragma unroll
    for (int kc = 0; kc < K / KC; kc++) {
        // coalesced load of A chunk [256 rows x 16 k] (transposed into As[k][r])
        #pragma unroll
        for (int u = 0; u < 4; u++) {
            int slot = u * 256 + tid;        // 0..1023
            int r  = slot >> 2;              // 0..255
            int c4 = slot & 3;
            float4 v = make_float4(0.f, 0.f, 0.f, 0.f);
            if (rowBase + r < n)
                v = *reinterpret_cast<const float4*>(A + (size_t)(rowBase + r) * K + kc * KC + c4 * 4);
            As[c4 * 4 + 0][r] = v.x;
            As[c4 * 4 + 1][r] = v.y;
            As[c4 * 4 + 2][r] = v.z;
            As[c4 * 4 + 3][r] = v.w;
        }
        __syncthreads();

        #pragma unroll
        for (int k = 0; k < KC; k++) {
            int kg = kc * KC + k;
            float t = As[k][tid] * sScale[kg] + sShift[kg];
            t = (t > 0.f) ? t : expm1f(t);
            unsigned long long td = pack2_dup(t);
            #pragma unroll
            for (int m = 0; m < M / 2; m++)
                acc2[m] = fma2(td, sW2[kg * (M / 2) + m], acc2[m]);
        }
        __syncthreads();
    }

    // stage output in smem (row stride OROW floats), then coalesced stores
    unsigned long long* so = reinterpret_cast<unsigned long long*>(buf);
    #pragma unroll
    for (int m = 0; m < M / 2; m++)
        so[(size_t)tid * (OROW / 2) + m] = acc2[m];
    __syncthreads();

    const float* sf = reinterpret_cast<const float*>(buf);
    constexpr int Q = M / 4;                  // float4 per row
    #pragma unroll
    for (int u = 0; u < Q; u++) {
        int slot = u * 256 + tid;             // 0 .. 256*Q-1
        int r = slot / Q;
        int q = slot - r * Q;
        if (rowBase + r < n) {
            const float* s = sf + (size_t)r * OROW + q * 4;
            *reinterpret_cast<float4*>(C + (size_t)(rowBase + r) * M + q * 4) =
                make_float4(s[0], s[1], s[2], s[3]);
        }
    }
}

// ---------------- BN+ELU elementwise on h3 (16-dim) -> h3n ----------------
__global__ __launch_bounds__(256) void bn_elu16_kernel(
    const float* __restrict__ h, const float* __restrict__ stats,
    const float* __restrict__ gamma, const float* __restrict__ beta,
    float* __restrict__ hn, int n)
{
    int idx = blockIdx.x * blockDim.x + threadIdx.x;
    if (idx >= n * H3) return;
    int f = idx & 15;
    float invN = 1.f / (float)n;
    float mean = stats[f] * invN;
    float var  = stats[64 + f] * invN - mean * mean;
    float inv  = rsqrtf(var + BN_EPS);
    float sc = inv * __ldg(gamma + f);
    float sh = __ldg(beta + f) - mean * sc;
    float v = h[idx] * sc + sh;
    hn[idx] = (v > 0.f) ? v : expm1f(v);
}

// ---------------- final: SpMM(16) -> GEMM 16x40 -> log_softmax -> d_out ----------------
// (A @ h3n) @ W4 == A @ (h3n @ W4): gather 16-dim instead of 40-dim.
__global__ __launch_bounds__(256) void spmm16_gemm40_lsm_kernel(
    const float* __restrict__ hn, const int* __restrict__ col,
    const float* __restrict__ val, const float* __restrict__ W4,
    float* __restrict__ out, int n)
{
    __shared__ float sW[H3 * OUTD];   // 16 x 40 = 640 floats
    for (int i = threadIdx.x; i < H3 * OUTD; i += blockDim.x) sW[i] = W4[i];
    __syncthreads();

    int gw = (blockIdx.x * blockDim.x + threadIdx.x) >> 5;
    int lane = threadIdx.x & 31;
    if (gw >= n) return;

    int e0 = g_rowptr[gw], e1 = g_rowptr[gw + 1];
    int half = lane >> 4;
    int f    = lane & 15;

    // gather 16-dim aggregation, two edges in flight (half-warps)
    float acc = 0.f;
    #pragma unroll 2
    for (int e = e0 + half; e < e1; e += 2) {
        int   c = __ldg(col + e);
        float v = __ldg(val + e);
        acc += v * __ldg(hn + (size_t)c * 16 + f);
    }
    acc += __shfl_xor_sync(0xffffffffu, acc, 16);   // lanes k and k+16 now hold agg[k]

    // tiny GEMM: out[j] = sum_k agg[k] * W4[k][j]
    bool second = (lane < 8);
    float o0 = 0.f, o1 = 0.f;
    #pragma unroll
    for (int k = 0; k < 16; k++) {
        float ak = __shfl_sync(0xffffffffu, acc, k);
        o0 += ak * sW[k * OUTD + lane];
        if (second) o1 += ak * sW[k * OUTD + 32 + lane];
    }

    // log_softmax over 40
    float m = o0;
    if (second) m = fmaxf(m, o1);
    #pragma unroll
    for (int off = 16; off > 0; off >>= 1)
        m = fmaxf(m, __shfl_xor_sync(0xffffffffu, m, off));
    float s = __expf(o0 - m);
    if (second) s += __expf(o1 - m);
    #pragma unroll
    for (int off = 16; off > 0; off >>= 1)
        s += __shfl_xor_sync(0xffffffffu, s, off);
    float lse = m + logf(s);
    out[(size_t)gw * 40 + lane] = o0 - lse;
    if (second) out[(size_t)gw * 40 + 32 + lane] = o1 - lse;
}

// ---------------- launch ----------------
extern "C" void kernel_launch(void* const* d_in, const int* in_sizes, int n_in,
                              void* d_out, int out_size) {
    const float* x        = (const float*)d_in[0];
    const int*   edge_row = (const int*)  d_in[1];
    const int*   edge_col = (const int*)  d_in[2];
    const float* edge_val = (const float*)d_in[3];
    const float* W1 = (const float*)d_in[4];
    const float* W2 = (const float*)d_in[5];
    const float* W3 = (const float*)d_in[6];
    const float* W4 = (const float*)d_in[7];
    const float* g1 = (const float*)d_in[8];
    const float* b1 = (const float*)d_in[9];
    const float* g2 = (const float*)d_in[10];
    const float* b2 = (const float*)d_in[11];
    const float* g3 = (const float*)d_in[12];
    const float* b3 = (const float*)d_in[13];
    float* out = (float*)d_out;

    int n = in_sizes[0] / IN_DIM;   // 100000
    int e = in_sizes[1];            // 3200000

    float* sup1; cudaGetSymbolAddress((void**)&sup1, g_sup1);
    float* h1;   cudaGetSymbolAddress((void**)&h1,   g_h1);
    float* sup2; cudaGetSymbolAddress((void**)&sup2, g_sup2);
    float* h2;   cudaGetSymbolAddress((void**)&h2,   g_h2);
    float* sup3; cudaGetSymbolAddress((void**)&sup3, g_sup3);
    float* h3;   cudaGetSymbolAddress((void**)&h3,   g_h3);
    float* h3n;  cudaGetSymbolAddress((void**)&h3n,  g_h3n);
    float* stats; cudaGetSymbolAddress((void**)&stats, g_stats);
    float* stA = stats, *stB = stats + 128, *stC = stats + 256;

    const int SPMM_GRID = 592;  // 4 blocks/SM

    // 1: rowptr + zero stats
    setup_kernel<<<(e + 255) / 256, 256>>>(edge_row, n, e);
    // 2: layer-1 dense GEMM (scalar FFMA, proven)
    gemm512x64_kernel<<<(n + 63) / 64, 256>>>(x, W1, sup1, n);
    // 3: SpMM(64) + stats A
    spmm_stats_kernel<64><<<SPMM_GRID, 256>>>(sup1, edge_col, edge_val, h1, stA, n);
    // 4: bn_elu(A) + GEMM 64->32 (smem-staged)
    bn_gemm_kernel<64, 32><<<(n + 255) / 256, 256>>>(h1, stA, g1, b1, W2, sup2, n);
    // 5: SpMM(32) + stats B
    spmm_stats_kernel<32><<<SPMM_GRID, 256>>>(sup2, edge_col, edge_val, h2, stB, n);
    // 6: bn_elu(B) + GEMM 32->16 (smem-staged)
    bn_gemm_kernel<32, 16><<<(n + 255) / 256, 256>>>(h2, stB, g2, b2, W3, sup3, n);
    // 7: SpMM(16) + stats C
    spmm_stats_kernel<16><<<SPMM_GRID, 256>>>(sup3, edge_col, edge_val, h3, stC, n);
    // 8: bn_elu on h3 -> h3n
    bn_elu16_kernel<<<((size_t)n * 16 + 255) / 256, 256>>>(h3, stC, g3, b3, h3n, n);
    // 9: SpMM(16) + 16x40 GEMM + log_softmax (reordered layer 4)
    spmm16_gemm40_lsm_kernel<<<((size_t)n * 32 + 255) / 256, 256>>>(h3n, edge_col, edge_val, W4, out, n);
}

// round 11
// speedup vs baseline: 2.0506x; 1.0132x over previous
#include <cuda_runtime.h>
#include <cuda_bf16.h>
#include <math.h>
#include <stdint.h>

#define NN 100000
#define EE 3200000
#define IN_DIM 512
#define H1 64
#define H2 32
#define H3 16
#define OUTD 40
#define BN_EPS 1e-5f

// ---------------- scratch (device globals: allocation-free) ----------------
__device__ float g_sup1[NN * H1];
__device__ float g_h1  [NN * H1];
__device__ float g_sup2[NN * H2];
__device__ float g_h2  [NN * H2];
__device__ float g_sup3[NN * H3];
__device__ float g_h3  [NN * H3];
__device__ float g_h3n [NN * H3];
__device__ int   g_rowptr[NN + 1];
__device__ float g_stats[384];   // A(+0), B(+128), C(+256): sum[f], sumsq[64+f]

// ---------------- setup: zero stats + CSR rowptr (edge_row sorted) ----------------
__global__ void setup_kernel(const int* __restrict__ row, int n, int e) {
    int z = blockIdx.x * blockDim.x + threadIdx.x;
    if (z < 384) g_stats[z] = 0.f;
    int i = z;
    if (i >= e) return;
    int r = row[i];
    int prev = (i == 0) ? -1 : row[i - 1];
    for (int q = prev + 1; q <= r; q++) g_rowptr[q] = i;
    if (i == e - 1) {
        for (int q = r + 1; q <= n; q++) g_rowptr[q] = e;
    }
}

// ---------------- big GEMM: C[n x 64] = A[n x 512] @ B[512 x 64] ----------------
// BM=64, BN=64, BK=32, 256 threads, 4x4 micro-tile (fp32 FFMA roofline; proven).
__global__ __launch_bounds__(256) void gemm512x64_kernel(
    const float* __restrict__ A, const float* __restrict__ B,
    float* __restrict__ C, int n)
{
    __shared__ __align__(16) float As[32][68];
    __shared__ __align__(16) float Bs[32][64];

    int tid = threadIdx.x;
    int tx = tid & 15;
    int ty = tid >> 4;
    int rowBase = blockIdx.x * 64;

    int ar  = tid >> 3;
    int ac4 = tid & 7;
    int bk  = tid >> 4;
    int bn4 = tid & 15;

    float acc[4][4] = {};

    for (int k0 = 0; k0 < IN_DIM; k0 += 32) {
        #pragma unroll
        for (int rr = 0; rr < 2; rr++) {
            int r = ar + rr * 32;
            int grow = rowBase + r;
            float4 v = make_float4(0.f, 0.f, 0.f, 0.f);
            if (grow < n)
                v = *reinterpret_cast<const float4*>(A + (size_t)grow * IN_DIM + k0 + ac4 * 4);
            As[ac4 * 4 + 0][r] = v.x;
            As[ac4 * 4 + 1][r] = v.y;
            As[ac4 * 4 + 2][r] = v.z;
            As[ac4 * 4 + 3][r] = v.w;
        }
        #pragma unroll
        for (int kk2 = 0; kk2 < 2; kk2++) {
            int k = bk + kk2 * 16;
            float4 v = *reinterpret_cast<const float4*>(B + (size_t)(k0 + k) * 64 + bn4 * 4);
            *reinterpret_cast<float4*>(&Bs[k][bn4 * 4]) = v;
        }
        __syncthreads();

        #pragma unroll
        for (int kk = 0; kk < 32; kk++) {
            float a[4], b[4];
            *reinterpret_cast<float4*>(a) = *reinterpret_cast<const float4*>(&As[kk][ty * 4]);
            *reinterpret_cast<float4*>(b) = *reinterpret_cast<const float4*>(&Bs[kk][tx * 4]);
            #pragma unroll
            for (int i = 0; i < 4; i++)
                #pragma unroll
                for (int j = 0; j < 4; j++)
                    acc[i][j] += a[i] * b[j];
        }
        __syncthreads();
    }

    #pragma unroll
    for (int i = 0; i < 4; i++) {
        int grow = rowBase + ty * 4 + i;
        if (grow < n) {
            *reinterpret_cast<float4*>(C + (size_t)grow * 64 + tx * 4) =
                make_float4(acc[i][0], acc[i][1], acc[i][2], acc[i][3]);
        }
    }
}

// ---------------- persistent SpMM fused with BN-stats accumulation ----------------
template <int F>
__global__ __launch_bounds__(256) void spmm_stats_kernel(
    const float* __restrict__ sup, const int* __restrict__ col,
    const float* __restrict__ val, float* __restrict__ out,
    float* __restrict__ stats, int n)
{
    int wid  = threadIdx.x >> 5;
    int lane = threadIdx.x & 31;

    if constexpr (F == 64) {
        __shared__ float sm[8][64];
        const float2* s2 = reinterpret_cast<const float2*>(sup);
        float2* o2 = reinterpret_cast<float2*>(out);
        float sx = 0.f, sy = 0.f, qx = 0.f, qy = 0.f;
        for (int r = blockIdx.x * 8 + wid; r < n; r += gridDim.x * 8) {
            int e = g_rowptr[r], eend = g_rowptr[r + 1];
            float2 acc = make_float2(0.f, 0.f);
            #pragma unroll 4
            for (; e < eend; e++) {
                int   c = __ldg(col + e);
                float v = __ldg(val + e);
                float2 sv = __ldg(s2 + (size_t)c * 32 + lane);
                acc.x += v * sv.x;
                acc.y += v * sv.y;
            }
            o2[(size_t)r * 32 + lane] = acc;
            sx += acc.x; sy += acc.y;
            qx += acc.x * acc.x; qy += acc.y * acc.y;
        }
        sm[wid][2 * lane] = sx; sm[wid][2 * lane + 1] = sy;
        __syncthreads();
        if (threadIdx.x < 64) {
            float s = 0.f;
            #pragma unroll
            for (int w = 0; w < 8; w++) s += sm[w][threadIdx.x];
            atomicAdd(&stats[threadIdx.x], s);
        }
        __syncthreads();
        sm[wid][2 * lane] = qx; sm[wid][2 * lane + 1] = qy;
        __syncthreads();
        if (threadIdx.x < 64) {
            float s = 0.f;
            #pragma unroll
            for (int w = 0; w < 8; w++) s += sm[w][threadIdx.x];
            atomicAdd(&stats[64 + threadIdx.x], s);
        }
    } else if constexpr (F == 32) {
        __shared__ float sm[8][32];
        float sx = 0.f, qx = 0.f;
        for (int r = blockIdx.x * 8 + wid; r < n; r += gridDim.x * 8) {
            int e = g_rowptr[r], eend = g_rowptr[r + 1];
            float acc = 0.f;
            #pragma unroll 4
            for (; e < eend; e++) {
                int   c = __ldg(col + e);
                float v = __ldg(val + e);
                acc += v * __ldg(sup + (size_t)c * 32 + lane);
            }
            out[(size_t)r * 32 + lane] = acc;
            sx += acc; qx += acc * acc;
        }
        sm[wid][lane] = sx;
        __syncthreads();
        if (threadIdx.x < 32) {
            float s = 0.f;
            #pragma unroll
            for (int w = 0; w < 8; w++) s += sm[w][threadIdx.x];
            atomicAdd(&stats[threadIdx.x], s);
        }
        __syncthreads();
        sm[wid][lane] = qx;
        __syncthreads();
        if (threadIdx.x < 32) {
            float s = 0.f;
            #pragma unroll
            for (int w = 0; w < 8; w++) s += sm[w][threadIdx.x];
            atomicAdd(&stats[64 + threadIdx.x], s);
        }
    } else {  // F == 16: two rows per warp (half-warps)
        __shared__ float sm[8][32];
        int half = lane >> 4;
        int f    = lane & 15;
        float sx = 0.f, qx = 0.f;
        for (int r = blockIdx.x * 16 + wid * 2 + half; r < n; r += gridDim.x * 16) {
            int e = g_rowptr[r], eend = g_rowptr[r + 1];
            float acc = 0.f;
            #pragma unroll 4
            for (; e < eend; e++) {
                int   c = __ldg(col + e);
                float v = __ldg(val + e);
                acc += v * __ldg(sup + (size_t)c * 16 + f);
            }
            out[(size_t)r * 16 + f] = acc;
            sx += acc; qx += acc * acc;
        }
        sm[wid][lane] = sx;
        __syncthreads();
        if (threadIdx.x < 16) {
            float s = 0.f;
            #pragma unroll
            for (int w = 0; w < 8; w++) s += sm[w][threadIdx.x] + sm[w][threadIdx.x + 16];
            atomicAdd(&stats[threadIdx.x], s);
        }
        __syncthreads();
        sm[wid][lane] = qx;
        __syncthreads();
        if (threadIdx.x < 16) {
            float s = 0.f;
            #pragma unroll
            for (int w = 0; w < 8; w++) s += sm[w][threadIdx.x] + sm[w][threadIdx.x + 16];
            atomicAdd(&stats[64 + threadIdx.x], s);
        }
    }
}

// ---------------- fused BN+ELU+GEMM, tiled: C[n x M] = elu(bn(A)) @ W ----------------
// BM=128, full K in smem (K<=64 -> single load phase), BN+ELU applied on A-tile load.
// Micro-tile: M=32 -> 4x4 (tx 0..7, ty 0..31); M=16 -> 2x4 (tx 0..3, ty 0..63).
template <int K, int M>
__global__ __launch_bounds__(256) void bn_gemm_kernel(
    const float* __restrict__ A, const float* __restrict__ stats,
    const float* __restrict__ gamma, const float* __restrict__ beta,
    const float* __restrict__ W, float* __restrict__ C, int n)
{
    constexpr int BM = 128;
    constexpr int AROW = BM + 4;              // 132 floats: 528B rows, 16B-aligned
    constexpr int WPAD = M + 4;               // 36 or 20 floats: 16B-aligned rows
    constexpr int TC = M / 4;                 // col groups: 8 or 4
    constexpr int TR = BM / (256 / TC);       // rows/thread: 4 or 2

    __shared__ __align__(16) float As[K][AROW];
    __shared__ __align__(16) float Ws[K][WPAD];
    __shared__ float sScale[K], sShift[K];

    int tid = threadIdx.x;
    int rowBase = blockIdx.x * BM;

    // scale/shift + W into smem
    if (tid < K) {
        float invN = 1.f / (float)n;
        float mean = stats[tid] * invN;
        float var  = stats[64 + tid] * invN - mean * mean;
        float inv  = rsqrtf(var + BN_EPS);
        float sc = inv * gamma[tid];
        sScale[tid] = sc;
        sShift[tid] = beta[tid] - mean * sc;
    }
    for (int i = tid; i < K * M; i += 256)
        Ws[i / M][i % M] = W[i];
    __syncthreads();

    // A tile load (coalesced float4), BN+ELU applied, transposed into As[k][r]
    constexpr int NF4 = BM * (K / 4) / 256;   // 8 (K=64) or 4 (K=32)
    #pragma unroll
    for (int u = 0; u < NF4; u++) {
        int slot = u * 256 + tid;
        int r  = slot / (K / 4);
        int c4 = slot % (K / 4);
        float4 v = make_float4(0.f, 0.f, 0.f, 0.f);
        if (rowBase + r < n)
            v = *reinterpret_cast<const float4*>(A + (size_t)(rowBase + r) * K + c4 * 4);
        int k = c4 * 4;
        float t0 = v.x * sScale[k + 0] + sShift[k + 0];
        float t1 = v.y * sScale[k + 1] + sShift[k + 1];
        float t2 = v.z * sScale[k + 2] + sShift[k + 2];
        float t3 = v.w * sScale[k + 3] + sShift[k + 3];
        As[k + 0][r] = (t0 > 0.f) ? t0 : expm1f(t0);
        As[k + 1][r] = (t1 > 0.f) ? t1 : expm1f(t1);
        As[k + 2][r] = (t2 > 0.f) ? t2 : expm1f(t2);
        As[k + 3][r] = (t3 > 0.f) ? t3 : expm1f(t3);
    }
    __syncthreads();

    int tx = tid % TC;
    int ty = tid / TC;

    float acc[TR][4];
    #pragma unroll
    for (int i = 0; i < TR; i++)
        #pragma unroll
        for (int j = 0; j < 4; j++) acc[i][j] = 0.f;

    #pragma unroll 16
    for (int k = 0; k < K; k++) {
        float b[4];
        *reinterpret_cast<float4*>(b) = *reinterpret_cast<const float4*>(&Ws[k][tx * 4]);
        float a[TR];
        if constexpr (TR == 4) {
            *reinterpret_cast<float4*>(a) = *reinterpret_cast<const float4*>(&As[k][ty * 4]);
        } else {
            *reinterpret_cast<float2*>(a) = *reinterpret_cast<const float2*>(&As[k][ty * 2]);
        }
        #pragma unroll
        for (int i = 0; i < TR; i++)
            #pragma unroll
            for (int j = 0; j < 4; j++)
                acc[i][j] += a[i] * b[j];
    }

    #pragma unroll
    for (int i = 0; i < TR; i++) {
        int row = rowBase + ty * TR + i;
        if (row < n) {
            *reinterpret_cast<float4*>(C + (size_t)row * M + tx * 4) =
                make_float4(acc[i][0], acc[i][1], acc[i][2], acc[i][3]);
        }
    }
}

// ---------------- BN+ELU elementwise on h3 (16-dim) -> h3n ----------------
__global__ __launch_bounds__(256) void bn_elu16_kernel(
    const float* __restrict__ h, const float* __restrict__ stats,
    const float* __restrict__ gamma, const float* __restrict__ beta,
    float* __restrict__ hn, int n)
{
    int idx = blockIdx.x * blockDim.x + threadIdx.x;
    if (idx >= n * H3) return;
    int f = idx & 15;
    float invN = 1.f / (float)n;
    float mean = stats[f] * invN;
    float var  = stats[64 + f] * invN - mean * mean;
    float inv  = rsqrtf(var + BN_EPS);
    float sc = inv * __ldg(gamma + f);
    float sh = __ldg(beta + f) - mean * sc;
    float v = h[idx] * sc + sh;
    hn[idx] = (v > 0.f) ? v : expm1f(v);
}

// ---------------- final: SpMM(16) -> GEMM 16x40 -> log_softmax -> d_out ----------------
__global__ __launch_bounds__(256) void spmm16_gemm40_lsm_kernel(
    const float* __restrict__ hn, const int* __restrict__ col,
    const float* __restrict__ val, const float* __restrict__ W4,
    float* __restrict__ out, int n)
{
    __shared__ float sW[H3 * OUTD];   // 16 x 40 = 640 floats
    for (int i = threadIdx.x; i < H3 * OUTD; i += blockDim.x) sW[i] = W4[i];
    __syncthreads();

    int gw = (blockIdx.x * blockDim.x + threadIdx.x) >> 5;
    int lane = threadIdx.x & 31;
    if (gw >= n) return;

    int e0 = g_rowptr[gw], e1 = g_rowptr[gw + 1];
    int half = lane >> 4;
    int f    = lane & 15;

    float acc = 0.f;
    #pragma unroll 2
    for (int e = e0 + half; e < e1; e += 2) {
        int   c = __ldg(col + e);
        float v = __ldg(val + e);
        acc += v * __ldg(hn + (size_t)c * 16 + f);
    }
    acc += __shfl_xor_sync(0xffffffffu, acc, 16);

    bool second = (lane < 8);
    float o0 = 0.f, o1 = 0.f;
    #pragma unroll
    for (int k = 0; k < 16; k++) {
        float ak = __shfl_sync(0xffffffffu, acc, k);
        o0 += ak * sW[k * OUTD + lane];
        if (second) o1 += ak * sW[k * OUTD + 32 + lane];
    }

    float m = o0;
    if (second) m = fmaxf(m, o1);
    #pragma unroll
    for (int off = 16; off > 0; off >>= 1)
        m = fmaxf(m, __shfl_xor_sync(0xffffffffu, m, off));
    float s = __expf(o0 - m);
    if (second) s += __expf(o1 - m);
    #pragma unroll
    for (int off = 16; off > 0; off >>= 1)
        s += __shfl_xor_sync(0xffffffffu, s, off);
    float lse = m + logf(s);
    out[(size_t)gw * 40 + lane] = o0 - lse;
    if (second) out[(size_t)gw * 40 + 32 + lane] = o1 - lse;
}

// ---------------- launch ----------------
extern "C" void kernel_launch(void* const* d_in, const int* in_sizes, int n_in,
                              void* d_out, int out_size) {
    const float* x        = (const float*)d_in[0];
    const int*   edge_row = (const int*)  d_in[1];
    const int*   edge_col = (const int*)  d_in[2];
    const float* edge_val = (const float*)d_in[3];
    const float* W1 = (const float*)d_in[4];
    const float* W2 = (const float*)d_in[5];
    const float* W3 = (const float*)d_in[6];
    const float* W4 = (const float*)d_in[7];
    const float* g1 = (const float*)d_in[8];
    const float* b1 = (const float*)d_in[9];
    const float* g2 = (const float*)d_in[10];
    const float* b2 = (const float*)d_in[11];
    const float* g3 = (const float*)d_in[12];
    const float* b3 = (const float*)d_in[13];
    float* out = (float*)d_out;

    int n = in_sizes[0] / IN_DIM;   // 100000
    int e = in_sizes[1];            // 3200000

    float* sup1; cudaGetSymbolAddress((void**)&sup1, g_sup1);
    float* h1;   cudaGetSymbolAddress((void**)&h1,   g_h1);
    float* sup2; cudaGetSymbolAddress((void**)&sup2, g_sup2);
    float* h2;   cudaGetSymbolAddress((void**)&h2,   g_h2);
    float* sup3; cudaGetSymbolAddress((void**)&sup3, g_sup3);
    float* h3;   cudaGetSymbolAddress((void**)&h3,   g_h3);
    float* h3n;  cudaGetSymbolAddress((void**)&h3n,  g_h3n);
    float* stats; cudaGetSymbolAddress((void**)&stats, g_stats);
    float* stA = stats, *stB = stats + 128, *stC = stats + 256;

    const int SPMM_GRID = 592;  // 4 blocks/SM

    // 1: rowptr + zero stats
    setup_kernel<<<(e + 255) / 256, 256>>>(edge_row, n, e);
    // 2: layer-1 dense GEMM (scalar FFMA roofline)
    gemm512x64_kernel<<<(n + 63) / 64, 256>>>(x, W1, sup1, n);
    // 3: SpMM(64) + stats A
    spmm_stats_kernel<64><<<SPMM_GRID, 256>>>(sup1, edge_col, edge_val, h1, stA, n);
    // 4: bn_elu(A) + GEMM 64->32 (tiled)
    bn_gemm_kernel<64, 32><<<(n + 127) / 128, 256>>>(h1, stA, g1, b1, W2, sup2, n);
    // 5: SpMM(32) + stats B
    spmm_stats_kernel<32><<<SPMM_GRID, 256>>>(sup2, edge_col, edge_val, h2, stB, n);
    // 6: bn_elu(B) + GEMM 32->16 (tiled)
    bn_gemm_kernel<32, 16><<<(n + 127) / 128, 256>>>(h2, stB, g2, b2, W3, sup3, n);
    // 7: SpMM(16) + stats C
    spmm_stats_kernel<16><<<SPMM_GRID, 256>>>(sup3, edge_col, edge_val, h3, stC, n);
    // 8: bn_elu on h3 -> h3n
    bn_elu16_kernel<<<((size_t)n * 16 + 255) / 256, 256>>>(h3, stC, g3, b3, h3n, n);
    // 9: SpMM(16) + 16x40 GEMM + log_softmax (reordered layer 4)
    spmm16_gemm40_lsm_kernel<<<((size_t)n * 32 + 255) / 256, 256>>>(h3n, edge_col, edge_val, W4, out, n);
}